// round 14
// baseline (speedup 1.0000x reference)
#include <cuda_runtime.h>
#include <math.h>

#define NB 64
#define IMG 224
#define HP 110
#define NPIX (IMG*IMG)
#define HG 320
#define WG 640

typedef unsigned long long ull;

// ---------------- scratch ----------------------------------------------------
__device__ float  g_xs[(size_t)NB * 3 * NPIX];        // x shifted by one element
__device__ float  g_h1[(size_t)NB * 6 * HP * HP];
__device__ float  g_radii[NB * HG];
__device__ float  g_unit[WG * 2];

// ---------------- f32x2 helpers ----------------------------------------------
__device__ __forceinline__ ull pk(float lo, float hi) {
    ull r; asm("mov.b64 %0,{%1,%2};" : "=l"(r) : "f"(lo), "f"(hi)); return r;
}
__device__ __forceinline__ float2 unpk(ull v) {
    float2 r; asm("mov.b64 {%0,%1},%2;" : "=f"(r.x), "=f"(r.y) : "l"(v)); return r;
}
__device__ __forceinline__ void fma2(ull& d, ull a, ull b) {
    asm("fma.rn.f32x2 %0,%1,%2,%0;" : "+l"(d) : "l"(a), "l"(b));
}

// ---------------- K1: xs[i] = x[i+1] shift + unit table ----------------------
__global__ void k_shift_unit(const float* __restrict__ x) {
    int blk = blockIdx.x;
    if (blk >= 9408) {
        int gx = (blk - 9408) * 256 + threadIdx.x;
        if (gx < WG) {
            float af = (float)(2.0 * M_PI) * (float)gx / 640.0f;
            g_unit[gx * 2 + 0] = sinf(af);
            g_unit[gx * 2 + 1] = cosf(af);
        }
        return;
    }
    int gid = blk * 256 + threadIdx.x;
    const int total = NB * 3 * NPIX / 4;
    float4 q0 = __ldg(reinterpret_cast<const float4*>(x) + gid);
    float4 q1 = make_float4(0.f, 0.f, 0.f, 0.f);
    if (gid + 1 < total) q1 = __ldg(reinterpret_cast<const float4*>(x) + gid + 1);
    float4 o; o.x = q0.y; o.y = q0.z; o.z = q0.w; o.w = q1.x;
    reinterpret_cast<float4*>(g_xs)[gid] = o;
}

// ---------------- K2: conv1 + maxpool, pair loads, LDS.128 weights ----------
__device__ __forceinline__ void loadrow(ull* P, const float* xrow, const float* xsrow) {
    longlong2 e01 = __ldg(reinterpret_cast<const longlong2*>(xrow));
    longlong2 e23 = __ldg(reinterpret_cast<const longlong2*>(xrow) + 1);
    longlong2 o01 = __ldg(reinterpret_cast<const longlong2*>(xsrow));
    ull       o2  = __ldg(reinterpret_cast<const ull*>(xsrow) + 2);
    P[0] = (ull)e01.x; P[1] = (ull)o01.x; P[2] = (ull)e01.y; P[3] = (ull)o01.y;
    P[4] = (ull)e23.x; P[5] = o2;         P[6] = (ull)e23.y;
}

__global__ void __launch_bounds__(128) k_conv1_v5(const float* __restrict__ x,
                                                  const float* __restrict__ w,
                                                  const float* __restrict__ bia) {
    __shared__ __align__(16) ull swd[600];   // [ci*25+ky*5+kx][8] (6 used)
    __shared__ float sb[6];
    int tid = threadIdx.x;
    for (int i = tid; i < 450; i += 128) {
        int co = i / 75, r = i % 75;
        float ww = w[i];
        swd[r * 8 + co] = pk(ww, ww);
    }
    if (tid < 6) sb[tid] = bia[tid];
    __syncthreads();

    int b = blockIdx.y;
    int pos2 = blockIdx.x * 128 + tid;
    if (pos2 >= 55 * HP) return;
    int py = pos2 / 55, pxp = pos2 % 55;
    int px0 = 2 * pxp;
    size_t rowoff = (size_t)(2 * py) * IMG + 4 * pxp;
    const float* xb  = x    + (size_t)b * 3 * NPIX + rowoff;
    const float* xsb = g_xs + (size_t)b * 3 * NPIX + rowoff;

    ull acc[6][4];
    #pragma unroll
    for (int co = 0; co < 6; co++)
        #pragma unroll
        for (int q = 0; q < 4; q++) acc[co][q] = 0ull;

    #pragma unroll 1
    for (int ci = 0; ci < 3; ci++) {
        const float* xc  = xb  + (size_t)ci * NPIX;
        const float* xsc = xsb + (size_t)ci * NPIX;
        ull P[2][7];
        loadrow(P[0], xc, xsc);
        #pragma unroll
        for (int ky = 0; ky < 5; ky++) {
            loadrow(P[(ky + 1) & 1], xc + (ky + 1) * IMG, xsc + (ky + 1) * IMG);
            const ull* PA = P[ky & 1];
            const ull* PB = P[(ky + 1) & 1];
            #pragma unroll
            for (int kx = 0; kx < 5; kx++) {
                const ull* wr = swd + (ci * 25 + ky * 5 + kx) * 8;
                ulonglong2 w01 = *reinterpret_cast<const ulonglong2*>(wr);
                ulonglong2 w23 = *reinterpret_cast<const ulonglong2*>(wr + 2);
                ulonglong2 w45 = *reinterpret_cast<const ulonglong2*>(wr + 4);
                ull pa = PA[kx], pb = PB[kx], pa2 = PA[kx + 2], pb2 = PB[kx + 2];
                fma2(acc[0][0], pa, w01.x); fma2(acc[0][1], pb, w01.x);
                fma2(acc[0][2], pa2, w01.x); fma2(acc[0][3], pb2, w01.x);
                fma2(acc[1][0], pa, w01.y); fma2(acc[1][1], pb, w01.y);
                fma2(acc[1][2], pa2, w01.y); fma2(acc[1][3], pb2, w01.y);
                fma2(acc[2][0], pa, w23.x); fma2(acc[2][1], pb, w23.x);
                fma2(acc[2][2], pa2, w23.x); fma2(acc[2][3], pb2, w23.x);
                fma2(acc[3][0], pa, w23.y); fma2(acc[3][1], pb, w23.y);
                fma2(acc[3][2], pa2, w23.y); fma2(acc[3][3], pb2, w23.y);
                fma2(acc[4][0], pa, w45.x); fma2(acc[4][1], pb, w45.x);
                fma2(acc[4][2], pa2, w45.x); fma2(acc[4][3], pb2, w45.x);
                fma2(acc[5][0], pa, w45.y); fma2(acc[5][1], pb, w45.y);
                fma2(acc[5][2], pa2, w45.y); fma2(acc[5][3], pb2, w45.y);
            }
        }
    }
    #pragma unroll
    for (int co = 0; co < 6; co++) {
        float2 u0 = unpk(acc[co][0]);
        float2 u1 = unpk(acc[co][1]);
        float2 u2 = unpk(acc[co][2]);
        float2 u3 = unpk(acc[co][3]);
        float2 m;
        m.x = fmaxf(fmaxf(u0.x, u0.y), fmaxf(u1.x, u1.y)) + sb[co];
        m.y = fmaxf(fmaxf(u2.x, u2.y), fmaxf(u3.x, u3.y)) + sb[co];
        *reinterpret_cast<float2*>(
            g_h1 + ((size_t)b * 6 + co) * (HP * HP) + (size_t)py * HP + px0) = m;
    }
}

// ---------------- K3: fused winsum + head + radii, 512 threads/batch --------
__global__ void __launch_bounds__(512) k_wh(const float* __restrict__ w2,
                                            const float* __restrict__ b2,
                                            const float* __restrict__ f1w,
                                            const float* __restrict__ f1b,
                                            const float* __restrict__ f2w,
                                            const float* __restrict__ f2b,
                                            float* __restrict__ outw) {
    int b = blockIdx.x, tid = threadIdx.x;
    __shared__ double sP[3][4][112];
    __shared__ double sC[3][5][112];
    __shared__ double sW[3][25][4];
    __shared__ double sS[150];
    __shared__ double sred[16][16];
    __shared__ double sfeat[16];
    __shared__ double sh8[8];
    __shared__ float  slog[2];

    #pragma unroll 1
    for (int pass = 0; pass < 2; pass++) {
        int cbase = pass * 3;
        // A: column chunk sums (28-row chunks, same order as winsum3)
        for (int t = tid; t < 1320; t += 512) {
            int cl = t / 440, rem = t % 440;
            int xcol = rem >> 2, chunk = rem & 3;
            const float* h = g_h1 + ((size_t)(b * 6 + cbase + cl)) * (HP * HP);
            int y0 = chunk * 28, y1 = min(y0 + 28, HP);
            double s = 0.0;
            for (int y = y0; y < y1; y++) s += (double)h[y * HP + xcol];
            sP[cl][chunk][xcol] = s;
        }
        __syncthreads();
        // B: 5 shifted column sums via edge subtraction
        for (int t = tid; t < 330; t += 512) {
            int cl = t / 110, xcol = t % 110;
            const float* h = g_h1 + ((size_t)(b * 6 + cbase + cl)) * (HP * HP);
            double F = (sP[cl][0][xcol] + sP[cl][1][xcol])
                     + (sP[cl][2][xcol] + sP[cl][3][xcol]);
            double b0 = (double)h[0 * HP + xcol], b1 = (double)h[1 * HP + xcol];
            double b2v = (double)h[2 * HP + xcol], b3 = (double)h[3 * HP + xcol];
            double e0 = (double)h[106 * HP + xcol], e1 = (double)h[107 * HP + xcol];
            double e2 = (double)h[108 * HP + xcol], e3 = (double)h[109 * HP + xcol];
            sC[cl][0][xcol] = F - e0 - e1 - e2 - e3;
            sC[cl][1][xcol] = F - b0 - e1 - e2 - e3;
            sC[cl][2][xcol] = F - b0 - b1 - e2 - e3;
            sC[cl][3][xcol] = F - b0 - b1 - b2v - e3;
            sC[cl][4][xcol] = F - b0 - b1 - b2v - b3;
        }
        __syncthreads();
        // C: window chunk sums (27-col chunks)
        for (int t = tid; t < 300; t += 512) {
            int cl = t / 100, rem = t % 100;
            int r = rem >> 2, ch = rem & 3;
            int ky = r / 5, kx = r % 5;
            int x0 = kx + ch * 27, x1 = kx + min(ch * 27 + 27, 106);
            double s = 0.0;
            for (int xx = x0; xx < x1; xx++) s += sC[cl][ky][xx];
            sW[cl][r][ch] = s;
        }
        __syncthreads();
        // D
        if (tid < 75) {
            int cl = tid / 25, r = tid % 25;
            sS[(cbase + cl) * 25 + r] =
                (sW[cl][r][0] + sW[cl][r][1]) + (sW[cl][r][2] + sW[cl][r][3]);
        }
        __syncthreads();
    }

    // E: feat, 16 slices per output
    if (tid < 256) {
        int o = tid >> 4, sl = tid & 15;
        double a = 0.0;
        for (int i = sl; i < 150; i += 16)
            a += (double)w2[o * 150 + i] * sS[i];
        sred[o][sl] = a;
    }
    __syncthreads();
    if (tid < 16) {
        double s = 0.0;
        #pragma unroll
        for (int k = 0; k < 16; k++) s += sred[tid][k];
        sfeat[tid] = s / 11236.0 + (double)b2[tid];
    }
    __syncthreads();
    // F: fc1 products in parallel
    if (tid < 128) {
        int j = tid >> 4, q = tid & 15;
        sred[j][q] = sfeat[q] * (double)f1w[j * 16 + q];
    }
    __syncthreads();
    if (tid < 8) {
        double acc = (double)f1b[tid];
        #pragma unroll
        for (int q = 0; q < 16; q++) acc += sred[tid][q];
        sh8[tid] = acc > 0.0 ? acc : 0.0;
    }
    __syncthreads();
    if (tid < 2) {
        double acc = (double)f2b[tid];
        #pragma unroll
        for (int j = 0; j < 8; j++) acc += sh8[j] * (double)f2w[tid * 8 + j];
        double s = 1.0 / (1.0 + exp(-acc));
        float wf = (float)(s * 5.0);
        outw[b * 2 + tid] = wf;
        float scaled = (tid == 0 ? 0.01f : 0.6f) * wf;
        slog[tid] = (float)log((double)scaled);
    }
    __syncthreads();

    float stf = slog[0];
    float dl  = slog[1] - slog[0];
    for (int gy = tid; gy < HG; gy += 512) {
        float t = (float)gy / 319.0f;
        g_radii[b * HG + gy] = expf(stf + dl * t);
    }
}

// ---------------- K4: grid sample, 16-angle x 2-radii warp patches ----------
__global__ void __launch_bounds__(640) k_sample4(const float* __restrict__ x,
                                                 const float* __restrict__ lt,
                                                 float* __restrict__ out) {
    __shared__ float  s_rad[10];
    __shared__ float2 s_unit[WG];
    __shared__ float  s_part[3][WG][2];
    int b  = blockIdx.y;
    int py = blockIdx.x;
    int t  = threadIdx.x;

    if (t < 10) s_rad[t] = g_radii[b * HG + py * 10 + t];
    s_unit[t] = reinterpret_cast<const float2*>(g_unit)[t];
    __syncthreads();

    float l0 = lt[b * 2 + 0];
    float l1 = lt[b * 2 + 1];
    const ull* xp  = reinterpret_cast<const ull*>(x    + (size_t)b * 3 * NPIX);
    const ull* xsp = reinterpret_cast<const ull*>(g_xs + (size_t)b * 3 * NPIX);
    const int RP = NPIX / 2;
    const int WP = IMG / 2;

    int lane = t & 31, w = t >> 5;
    int a16 = lane & 15, ri = lane >> 4;

    #pragma unroll
    for (int gi = 0; gi < 2; gi++) {
        int angle = (2 * w + gi) * 16 + a16;
        float us = s_unit[angle].x;
        float uc = s_unit[angle].y;
        float a0 = 0.f, a1 = 0.f, a2 = 0.f;
        #pragma unroll
        for (int p = 0; p < 5; p++) {
            float r = s_rad[p * 2 + ri];
            float gxx = r * us + l0;
            float gyy = r * uc + l1;
            float ix = ((gxx + 1.0f) * 224.0f - 1.0f) * 0.5f;
            float iy = ((gyy + 1.0f) * 224.0f - 1.0f) * 0.5f;
            float fx = floorf(ix), fy = floorf(iy);
            float wx = ix - fx,   wy = iy - fy;
            int x0 = min(max((int)fx, 0), 223);
            int x1 = min(max((int)fx + 1, 0), 223);
            int y0 = min(max((int)fy, 0), 223);
            int y1 = min(max((int)fy + 1, 0), 223);
            float w00 = (1.f - wx) * (1.f - wy);
            float w01 = wx * (1.f - wy);
            float w10 = (1.f - wx) * wy;
            float w11 = wx * wy;

            int xl = min(x0, 222);
            const ull* bp = (xl & 1) ? xsp : xp;
            int p0 = y0 * WP + (xl >> 1);
            int p1 = y1 * WP + (xl >> 1);
            bool hi0 = (x0 == 223);
            bool dup = (x1 == x0);

            #pragma unroll
            for (int c = 0; c < 3; c++) {
                float2 A  = unpk(__ldg(bp + c * RP + p0));
                float2 Bv = unpk(__ldg(bp + c * RP + p1));
                float v00 = hi0 ? A.y : A.x;
                float v01 = dup ? v00 : A.y;
                float v10 = hi0 ? Bv.y : Bv.x;
                float v11 = dup ? v10 : Bv.y;
                float sv = w00 * v00 + w01 * v01 + w10 * v10 + w11 * v11;
                if (c == 0) a0 += sv;
                else if (c == 1) a1 += sv;
                else a2 += sv;
            }
        }
        s_part[0][angle][ri] = a0;
        s_part[1][angle][ri] = a1;
        s_part[2][angle][ri] = a2;
    }
    __syncthreads();

    if (t < 192) {
        int c = t / 64, pw = t % 64;
        float s = 0.f;
        #pragma unroll
        for (int j = 0; j < 10; j++) {
            int a = pw * 10 + j;
            s += s_part[c][a][0] + s_part[c][a][1];
        }
        out[(((size_t)b * 3 + c) * 32 + py) * 64 + pw] = s * 0.01f;
    }
}

// ---------------- launch ------------------------------------------------------
extern "C" void kernel_launch(void* const* d_in, const int* in_sizes, int n_in,
                              void* d_out, int out_size) {
    const float* x   = (const float*)d_in[0];
    const float* lt  = (const float*)d_in[1];
    const float* c1w = (const float*)d_in[2];
    const float* c1b = (const float*)d_in[3];
    const float* c2w = (const float*)d_in[4];
    const float* c2b = (const float*)d_in[5];
    const float* f1w = (const float*)d_in[6];
    const float* f1b = (const float*)d_in[7];
    const float* f2w = (const float*)d_in[8];
    const float* f2b = (const float*)d_in[9];
    float* out = (float*)d_out;

    k_shift_unit<<<9411, 256>>>(x);                                        // #1
    k_conv1_v5<<<dim3((55 * HP + 127) / 128, NB), 128>>>(x, c1w, c1b);     // #2
    k_wh<<<NB, 512>>>(c2w, c2b, f1w, f1b, f2w, f2b,
                      out + 64 * 3 * 32 * 64);                             // #3
    k_sample4<<<dim3(32, NB), 640>>>(x, lt, out);                          // #4 -> profiled
}

// round 15
// speedup vs baseline: 1.1349x; 1.1349x over previous
#include <cuda_runtime.h>
#include <math.h>

#define NB 64
#define IMG 224
#define HP 110
#define NPIX (IMG*IMG)
#define HG 320
#define WG 640

typedef unsigned long long ull;

// ---------------- scratch ----------------------------------------------------
__device__ float  g_xs[(size_t)NB * 3 * NPIX];        // x shifted by one element
__device__ float  g_h1[(size_t)NB * 6 * HP * HP];
__device__ double g_S[NB * 6 * 25];
__device__ float  g_radii[NB * HG];
__device__ float  g_unit[WG * 2];

// ---------------- f32x2 helpers ----------------------------------------------
__device__ __forceinline__ ull pk(float lo, float hi) {
    ull r; asm("mov.b64 %0,{%1,%2};" : "=l"(r) : "f"(lo), "f"(hi)); return r;
}
__device__ __forceinline__ float2 unpk(ull v) {
    float2 r; asm("mov.b64 {%0,%1},%2;" : "=f"(r.x), "=f"(r.y) : "l"(v)); return r;
}
__device__ __forceinline__ void fma2(ull& d, ull a, ull b) {
    asm("fma.rn.f32x2 %0,%1,%2,%0;" : "+l"(d) : "l"(a), "l"(b));
}

// ---------------- K1: xs[i] = x[i+1] shift + unit table ----------------------
__global__ void k_shift_unit(const float* __restrict__ x) {
    int blk = blockIdx.x;
    if (blk >= 9408) {
        int gx = (blk - 9408) * 256 + threadIdx.x;
        if (gx < WG) {
            float af = (float)(2.0 * M_PI) * (float)gx / 640.0f;
            g_unit[gx * 2 + 0] = sinf(af);
            g_unit[gx * 2 + 1] = cosf(af);
        }
        return;
    }
    int gid = blk * 256 + threadIdx.x;
    const int total = NB * 3 * NPIX / 4;
    float4 q0 = __ldg(reinterpret_cast<const float4*>(x) + gid);
    float4 q1 = make_float4(0.f, 0.f, 0.f, 0.f);
    if (gid + 1 < total) q1 = __ldg(reinterpret_cast<const float4*>(x) + gid + 1);
    float4 o; o.x = q0.y; o.y = q0.z; o.z = q0.w; o.w = q1.x;
    reinterpret_cast<float4*>(g_xs)[gid] = o;
}

// ---------------- K2: conv1 + maxpool, pair loads, LDS.128 weights ----------
__device__ __forceinline__ void loadrow(ull* P, const float* xrow, const float* xsrow) {
    longlong2 e01 = __ldg(reinterpret_cast<const longlong2*>(xrow));
    longlong2 e23 = __ldg(reinterpret_cast<const longlong2*>(xrow) + 1);
    longlong2 o01 = __ldg(reinterpret_cast<const longlong2*>(xsrow));
    ull       o2  = __ldg(reinterpret_cast<const ull*>(xsrow) + 2);
    P[0] = (ull)e01.x; P[1] = (ull)o01.x; P[2] = (ull)e01.y; P[3] = (ull)o01.y;
    P[4] = (ull)e23.x; P[5] = o2;         P[6] = (ull)e23.y;
}

__global__ void __launch_bounds__(128) k_conv1_v5(const float* __restrict__ x,
                                                  const float* __restrict__ w,
                                                  const float* __restrict__ bia) {
    __shared__ __align__(16) ull swd[600];   // [ci*25+ky*5+kx][8] (6 used)
    __shared__ float sb[6];
    int tid = threadIdx.x;
    for (int i = tid; i < 450; i += 128) {
        int co = i / 75, r = i % 75;
        float ww = w[i];
        swd[r * 8 + co] = pk(ww, ww);
    }
    if (tid < 6) sb[tid] = bia[tid];
    __syncthreads();

    int b = blockIdx.y;
    int pos2 = blockIdx.x * 128 + tid;
    if (pos2 >= 55 * HP) return;
    int py = pos2 / 55, pxp = pos2 % 55;
    int px0 = 2 * pxp;
    size_t rowoff = (size_t)(2 * py) * IMG + 4 * pxp;
    const float* xb  = x    + (size_t)b * 3 * NPIX + rowoff;
    const float* xsb = g_xs + (size_t)b * 3 * NPIX + rowoff;

    ull acc[6][4];
    #pragma unroll
    for (int co = 0; co < 6; co++)
        #pragma unroll
        for (int q = 0; q < 4; q++) acc[co][q] = 0ull;

    #pragma unroll 1
    for (int ci = 0; ci < 3; ci++) {
        const float* xc  = xb  + (size_t)ci * NPIX;
        const float* xsc = xsb + (size_t)ci * NPIX;
        ull P[2][7];
        loadrow(P[0], xc, xsc);
        #pragma unroll
        for (int ky = 0; ky < 5; ky++) {
            loadrow(P[(ky + 1) & 1], xc + (ky + 1) * IMG, xsc + (ky + 1) * IMG);
            const ull* PA = P[ky & 1];
            const ull* PB = P[(ky + 1) & 1];
            #pragma unroll
            for (int kx = 0; kx < 5; kx++) {
                const ull* wr = swd + (ci * 25 + ky * 5 + kx) * 8;
                ulonglong2 w01 = *reinterpret_cast<const ulonglong2*>(wr);
                ulonglong2 w23 = *reinterpret_cast<const ulonglong2*>(wr + 2);
                ulonglong2 w45 = *reinterpret_cast<const ulonglong2*>(wr + 4);
                ull pa = PA[kx], pb = PB[kx], pa2 = PA[kx + 2], pb2 = PB[kx + 2];
                fma2(acc[0][0], pa, w01.x); fma2(acc[0][1], pb, w01.x);
                fma2(acc[0][2], pa2, w01.x); fma2(acc[0][3], pb2, w01.x);
                fma2(acc[1][0], pa, w01.y); fma2(acc[1][1], pb, w01.y);
                fma2(acc[1][2], pa2, w01.y); fma2(acc[1][3], pb2, w01.y);
                fma2(acc[2][0], pa, w23.x); fma2(acc[2][1], pb, w23.x);
                fma2(acc[2][2], pa2, w23.x); fma2(acc[2][3], pb2, w23.x);
                fma2(acc[3][0], pa, w23.y); fma2(acc[3][1], pb, w23.y);
                fma2(acc[3][2], pa2, w23.y); fma2(acc[3][3], pb2, w23.y);
                fma2(acc[4][0], pa, w45.x); fma2(acc[4][1], pb, w45.x);
                fma2(acc[4][2], pa2, w45.x); fma2(acc[4][3], pb2, w45.x);
                fma2(acc[5][0], pa, w45.y); fma2(acc[5][1], pb, w45.y);
                fma2(acc[5][2], pa2, w45.y); fma2(acc[5][3], pb2, w45.y);
            }
        }
    }
    #pragma unroll
    for (int co = 0; co < 6; co++) {
        float2 u0 = unpk(acc[co][0]);
        float2 u1 = unpk(acc[co][1]);
        float2 u2 = unpk(acc[co][2]);
        float2 u3 = unpk(acc[co][3]);
        float2 m;
        m.x = fmaxf(fmaxf(u0.x, u0.y), fmaxf(u1.x, u1.y)) + sb[co];
        m.y = fmaxf(fmaxf(u2.x, u2.y), fmaxf(u3.x, u3.y)) + sb[co];
        *reinterpret_cast<float2*>(
            g_h1 + ((size_t)b * 6 + co) * (HP * HP) + (size_t)py * HP + px0) = m;
    }
}

// ---------------- K3: winsum, chunk-parallel (double), 384 blocks ------------
__global__ void __launch_bounds__(512) k_winsum3() {
    int bc = blockIdx.x;                  // b*6 + c
    int tid = threadIdx.x;
    __shared__ double sP[4][112];
    __shared__ double sC[5][112];
    __shared__ double sW[25][4];

    const float* h = g_h1 + (size_t)bc * HP * HP;
    int chunk = tid >> 7, xcol = tid & 127;

    if (xcol < HP) {
        int y0 = chunk * 28, y1 = min(y0 + 28, HP);
        double s = 0.0;
        for (int y = y0; y < y1; y++) s += (double)h[y * HP + xcol];
        sP[chunk][xcol] = s;
    }
    __syncthreads();

    if (tid < HP) {
        double F = (sP[0][tid] + sP[1][tid]) + (sP[2][tid] + sP[3][tid]);
        double b0 = (double)h[0 * HP + tid], b1 = (double)h[1 * HP + tid];
        double b2 = (double)h[2 * HP + tid], b3 = (double)h[3 * HP + tid];
        double e0 = (double)h[106 * HP + tid], e1 = (double)h[107 * HP + tid];
        double e2 = (double)h[108 * HP + tid], e3 = (double)h[109 * HP + tid];
        sC[0][tid] = F - e0 - e1 - e2 - e3;
        sC[1][tid] = F - b0 - e1 - e2 - e3;
        sC[2][tid] = F - b0 - b1 - e2 - e3;
        sC[3][tid] = F - b0 - b1 - b2 - e3;
        sC[4][tid] = F - b0 - b1 - b2 - b3;
    }
    __syncthreads();

    if (tid < 100) {
        int r = tid >> 2, ch = tid & 3;
        int ky = r / 5, kx = r % 5;
        int x0 = kx + ch * 27, x1 = kx + min(ch * 27 + 27, 106);
        double s = 0.0;
        for (int xx = x0; xx < x1; xx++) s += sC[ky][xx];
        sW[r][ch] = s;
    }
    __syncthreads();

    if (tid < 25)
        g_S[bc * 25 + tid] = (sW[tid][0] + sW[tid][1]) + (sW[tid][2] + sW[tid][3]);
}

// ---------------- K4: head, contiguous slices + fp32 transcendentals ---------
__global__ void __launch_bounds__(256) k_head3(const float* __restrict__ w2,
                                               const float* __restrict__ b2,
                                               const float* __restrict__ f1w,
                                               const float* __restrict__ f1b,
                                               const float* __restrict__ f2w,
                                               const float* __restrict__ f2b,
                                               float* __restrict__ outw) {
    int b = blockIdx.x, tid = threadIdx.x;
    __shared__ double sred[16][15];
    __shared__ double sfeat[16];
    __shared__ double sprod[8][16];
    __shared__ double sh8[8];
    __shared__ float  slog[2];

    // E: feat = w2·S, 15 contiguous 10-element slices per output
    if (tid < 240) {
        int o = tid / 15, sl = tid % 15;
        const double* Sp = g_S + b * 150 + sl * 10;
        const float*  Wp = w2 + o * 150 + sl * 10;
        double v[10];
        #pragma unroll
        for (int k = 0; k < 10; k++) v[k] = (double)Wp[k] * Sp[k];
        double s01 = (v[0] + v[1]) + (v[2] + v[3]);
        double s23 = (v[4] + v[5]) + (v[6] + v[7]);
        sred[o][sl] = (s01 + s23) + (v[8] + v[9]);
    }
    __syncthreads();
    if (tid < 16) {
        double s = 0.0;
        #pragma unroll
        for (int k = 0; k < 15; k++) s += sred[tid][k];
        sfeat[tid] = s / 11236.0 + (double)b2[tid];
    }
    __syncthreads();

    // fc1 products in parallel
    if (tid < 128) {
        int j = tid >> 4, q = tid & 15;
        sprod[j][q] = sfeat[q] * (double)f1w[j * 16 + q];
    }
    __syncthreads();
    if (tid < 8) {
        double acc = (double)f1b[tid];
        #pragma unroll
        for (int q = 0; q < 16; q++) acc += sprod[tid][q];
        sh8[tid] = acc > 0.0 ? acc : 0.0;
    }
    __syncthreads();

    if (tid < 2) {
        double acc = (double)f2b[tid];
        #pragma unroll
        for (int j = 0; j < 8; j++) acc += sh8[j] * (double)f2w[tid * 8 + j];
        // fp32 sigmoid: |err| ~2ulp -> weight rel err ~2e-7, harmless
        float wf = 5.0f / (1.0f + expf(-(float)acc));
        outw[b * 2 + tid] = wf;
        float scaled = (tid == 0 ? 0.01f : 0.6f) * wf;
        slog[tid] = logf(scaled);
    }
    __syncthreads();

    float stf = slog[0];
    float dl  = slog[1] - slog[0];
    for (int gy = tid; gy < HG; gy += 256) {
        float t = (float)gy / 319.0f;
        g_radii[b * HG + gy] = expf(stf + dl * t);
    }
}

// ---------------- K5: grid sample, lane=angle, 64-bit pair gathers ----------
__global__ void __launch_bounds__(640) k_sample3(const float* __restrict__ x,
                                                 const float* __restrict__ lt,
                                                 float* __restrict__ out) {
    __shared__ float s_rad[10];
    __shared__ float s_acc[3][640];
    int b  = blockIdx.y;
    int py = blockIdx.x;
    int t  = threadIdx.x;

    if (t < 10) s_rad[t] = g_radii[b * HG + py * 10 + t];
    __syncthreads();

    float us = g_unit[t * 2 + 0];
    float uc = g_unit[t * 2 + 1];
    float l0 = lt[b * 2 + 0];
    float l1 = lt[b * 2 + 1];
    const ull* xp  = reinterpret_cast<const ull*>(x    + (size_t)b * 3 * NPIX);
    const ull* xsp = reinterpret_cast<const ull*>(g_xs + (size_t)b * 3 * NPIX);
    const int RP = NPIX / 2;
    const int WP = IMG / 2;

    float a0 = 0.f, a1 = 0.f, a2 = 0.f;
    #pragma unroll 1
    for (int i = 0; i < 10; i++) {
        float r = s_rad[i];
        float gxx = r * us + l0;
        float gyy = r * uc + l1;
        float ix = ((gxx + 1.0f) * 224.0f - 1.0f) * 0.5f;
        float iy = ((gyy + 1.0f) * 224.0f - 1.0f) * 0.5f;
        float fx = floorf(ix), fy = floorf(iy);
        float wx = ix - fx,   wy = iy - fy;
        int x0 = min(max((int)fx, 0), 223);
        int x1 = min(max((int)fx + 1, 0), 223);
        int y0 = min(max((int)fy, 0), 223);
        int y1 = min(max((int)fy + 1, 0), 223);
        float w00 = (1.f - wx) * (1.f - wy);
        float w01 = wx * (1.f - wy);
        float w10 = (1.f - wx) * wy;
        float w11 = wx * wy;

        int xl = min(x0, 222);
        const ull* bp = (xl & 1) ? xsp : xp;
        int p0 = y0 * WP + (xl >> 1);
        int p1 = y1 * WP + (xl >> 1);
        bool hi0 = (x0 == 223);
        bool dup = (x1 == x0);

        #pragma unroll
        for (int c = 0; c < 3; c++) {
            float2 A  = unpk(__ldg(bp + c * RP + p0));
            float2 Bv = unpk(__ldg(bp + c * RP + p1));
            float v00 = hi0 ? A.y : A.x;
            float v01 = dup ? v00 : A.y;
            float v10 = hi0 ? Bv.y : Bv.x;
            float v11 = dup ? v10 : Bv.y;
            float sv = w00 * v00 + w01 * v01 + w10 * v10 + w11 * v11;
            if (c == 0) a0 += sv;
            else if (c == 1) a1 += sv;
            else a2 += sv;
        }
    }
    s_acc[0][t] = a0;
    s_acc[1][t] = a1;
    s_acc[2][t] = a2;
    __syncthreads();

    if (t < 192) {
        int c = t / 64, pw = t % 64;
        const float* sp = &s_acc[c][pw * 10];
        float s = 0.f;
        #pragma unroll
        for (int j = 0; j < 10; j++) s += sp[j];
        out[(((size_t)b * 3 + c) * 32 + py) * 64 + pw] = s * 0.01f;
    }
}

// ---------------- launch ------------------------------------------------------
extern "C" void kernel_launch(void* const* d_in, const int* in_sizes, int n_in,
                              void* d_out, int out_size) {
    const float* x   = (const float*)d_in[0];
    const float* lt  = (const float*)d_in[1];
    const float* c1w = (const float*)d_in[2];
    const float* c1b = (const float*)d_in[3];
    const float* c2w = (const float*)d_in[4];
    const float* c2b = (const float*)d_in[5];
    const float* f1w = (const float*)d_in[6];
    const float* f1b = (const float*)d_in[7];
    const float* f2w = (const float*)d_in[8];
    const float* f2b = (const float*)d_in[9];
    float* out = (float*)d_out;

    k_shift_unit<<<9411, 256>>>(x);                                        // #1
    k_conv1_v5<<<dim3((55 * HP + 127) / 128, NB), 128>>>(x, c1w, c1b);     // #2
    k_winsum3<<<NB * 6, 512>>>();                                          // #3
    k_head3<<<NB, 256>>>(c2w, c2b, f1w, f1b, f2w, f2b,
                         out + 64 * 3 * 32 * 64);                          // #4 -> profiled
    k_sample3<<<dim3(32, NB), 640>>>(x, lt, out);                          // #5
}

// round 16
// speedup vs baseline: 1.2190x; 1.0741x over previous
#include <cuda_runtime.h>
#include <cuda_fp16.h>
#include <math.h>

#define NB 64
#define IMG 224
#define HP 110
#define NPIX (IMG*IMG)
#define HG 320
#define WG 640

typedef unsigned long long ull;

// ---------------- scratch ----------------------------------------------------
__device__ float  g_xs[(size_t)NB * 3 * NPIX];            // x shifted by one (fp32, conv)
__device__ ull    g_xh [(size_t)NB * 3 * NPIX / 4];       // fp16 x       (4 halves/ull)
__device__ ull    g_xhs[(size_t)NB * 3 * NPIX / 4];       // fp16 shifted (4 halves/ull)
__device__ float  g_h1[(size_t)NB * 6 * HP * HP];
__device__ double g_S[NB * 6 * 25];
__device__ float  g_radii[NB * HG];
__device__ float  g_unit[WG * 2];

// ---------------- f32x2 helpers ----------------------------------------------
__device__ __forceinline__ ull pk(float lo, float hi) {
    ull r; asm("mov.b64 %0,{%1,%2};" : "=l"(r) : "f"(lo), "f"(hi)); return r;
}
__device__ __forceinline__ float2 unpk(ull v) {
    float2 r; asm("mov.b64 {%0,%1},%2;" : "=f"(r.x), "=f"(r.y) : "l"(v)); return r;
}
__device__ __forceinline__ void fma2(ull& d, ull a, ull b) {
    asm("fma.rn.f32x2 %0,%1,%2,%0;" : "+l"(d) : "l"(a), "l"(b));
}

// ---------------- K1: xs/xh/xhs build + unit table ---------------------------
__global__ void k_shift_unit(const float* __restrict__ x) {
    int blk = blockIdx.x;
    if (blk >= 9408) {
        int gx = (blk - 9408) * 256 + threadIdx.x;
        if (gx < WG) {
            float af = (float)(2.0 * M_PI) * (float)gx / 640.0f;
            g_unit[gx * 2 + 0] = sinf(af);
            g_unit[gx * 2 + 1] = cosf(af);
        }
        return;
    }
    int gid = blk * 256 + threadIdx.x;     // float4 index; 9408*256 exact
    const int total = NB * 3 * NPIX / 4;
    float4 q0 = __ldg(reinterpret_cast<const float4*>(x) + gid);
    float4 q1 = make_float4(0.f, 0.f, 0.f, 0.f);
    if (gid + 1 < total) q1 = __ldg(reinterpret_cast<const float4*>(x) + gid + 1);
    float4 o; o.x = q0.y; o.y = q0.z; o.z = q0.w; o.w = q1.x;
    reinterpret_cast<float4*>(g_xs)[gid] = o;

    __half2 h0 = __floats2half2_rn(q0.x, q0.y);
    __half2 h1 = __floats2half2_rn(q0.z, q0.w);
    uint2 uh; uh.x = *reinterpret_cast<unsigned*>(&h0); uh.y = *reinterpret_cast<unsigned*>(&h1);
    reinterpret_cast<uint2*>(g_xh)[gid] = uh;

    __half2 s0 = __floats2half2_rn(o.x, o.y);
    __half2 s1 = __floats2half2_rn(o.z, o.w);
    uint2 us; us.x = *reinterpret_cast<unsigned*>(&s0); us.y = *reinterpret_cast<unsigned*>(&s1);
    reinterpret_cast<uint2*>(g_xhs)[gid] = us;
}

__global__ void k_nop1() {}
__global__ void k_nop2() {}

// ---------------- K2: conv1 + maxpool, co-split for occupancy ----------------
__device__ __forceinline__ void loadrow(ull* P, const float* xrow, const float* xsrow) {
    longlong2 e01 = __ldg(reinterpret_cast<const longlong2*>(xrow));
    longlong2 e23 = __ldg(reinterpret_cast<const longlong2*>(xrow) + 1);
    longlong2 o01 = __ldg(reinterpret_cast<const longlong2*>(xsrow));
    ull       o2  = __ldg(reinterpret_cast<const ull*>(xsrow) + 2);
    P[0] = (ull)e01.x; P[1] = (ull)o01.x; P[2] = (ull)e01.y; P[3] = (ull)o01.y;
    P[4] = (ull)e23.x; P[5] = o2;         P[6] = (ull)e23.y;
}

__global__ void __launch_bounds__(128) k_conv1_v6(const float* __restrict__ x,
                                                  const float* __restrict__ w,
                                                  const float* __restrict__ bia) {
    __shared__ __align__(16) ull swd[300];   // [r][4] (3 co used)
    __shared__ float sb[3];
    int tid = threadIdx.x;
    int cog = blockIdx.y;                    // co group: 0 -> co 0..2, 1 -> co 3..5
    for (int i = tid; i < 225; i += 128) {
        int co = i / 75, r = i % 75;
        float ww = w[(cog * 3 + co) * 75 + r];
        swd[r * 4 + co] = pk(ww, ww);
    }
    if (tid < 3) sb[tid] = bia[cog * 3 + tid];
    __syncthreads();

    int b = blockIdx.z;
    int pos2 = blockIdx.x * 128 + tid;
    if (pos2 >= 55 * HP) return;
    int py = pos2 / 55, pxp = pos2 % 55;
    int px0 = 2 * pxp;
    size_t rowoff = (size_t)(2 * py) * IMG + 4 * pxp;
    const float* xb  = x    + (size_t)b * 3 * NPIX + rowoff;
    const float* xsb = g_xs + (size_t)b * 3 * NPIX + rowoff;

    ull acc[3][4];
    #pragma unroll
    for (int co = 0; co < 3; co++)
        #pragma unroll
        for (int q = 0; q < 4; q++) acc[co][q] = 0ull;

    #pragma unroll 1
    for (int ci = 0; ci < 3; ci++) {
        const float* xc  = xb  + (size_t)ci * NPIX;
        const float* xsc = xsb + (size_t)ci * NPIX;
        ull P[2][7];
        loadrow(P[0], xc, xsc);
        #pragma unroll
        for (int ky = 0; ky < 5; ky++) {
            loadrow(P[(ky + 1) & 1], xc + (ky + 1) * IMG, xsc + (ky + 1) * IMG);
            const ull* PA = P[ky & 1];
            const ull* PB = P[(ky + 1) & 1];
            #pragma unroll
            for (int kx = 0; kx < 5; kx++) {
                const ull* wr = swd + (ci * 25 + ky * 5 + kx) * 4;
                ulonglong2 w01 = *reinterpret_cast<const ulonglong2*>(wr);
                ull        w2v = wr[2];
                ull pa = PA[kx], pb = PB[kx], pa2 = PA[kx + 2], pb2 = PB[kx + 2];
                fma2(acc[0][0], pa, w01.x); fma2(acc[0][1], pb, w01.x);
                fma2(acc[0][2], pa2, w01.x); fma2(acc[0][3], pb2, w01.x);
                fma2(acc[1][0], pa, w01.y); fma2(acc[1][1], pb, w01.y);
                fma2(acc[1][2], pa2, w01.y); fma2(acc[1][3], pb2, w01.y);
                fma2(acc[2][0], pa, w2v);   fma2(acc[2][1], pb, w2v);
                fma2(acc[2][2], pa2, w2v);  fma2(acc[2][3], pb2, w2v);
            }
        }
    }
    #pragma unroll
    for (int co = 0; co < 3; co++) {
        float2 u0 = unpk(acc[co][0]);
        float2 u1 = unpk(acc[co][1]);
        float2 u2 = unpk(acc[co][2]);
        float2 u3 = unpk(acc[co][3]);
        float2 m;
        m.x = fmaxf(fmaxf(u0.x, u0.y), fmaxf(u1.x, u1.y)) + sb[co];
        m.y = fmaxf(fmaxf(u2.x, u2.y), fmaxf(u3.x, u3.y)) + sb[co];
        *reinterpret_cast<float2*>(
            g_h1 + ((size_t)b * 6 + cog * 3 + co) * (HP * HP) + (size_t)py * HP + px0) = m;
    }
}

// ---------------- K3: winsum, chunk-parallel (double), 384 blocks ------------
__global__ void __launch_bounds__(512) k_winsum3() {
    int bc = blockIdx.x;
    int tid = threadIdx.x;
    __shared__ double sP[4][112];
    __shared__ double sC[5][112];
    __shared__ double sW[25][4];

    const float* h = g_h1 + (size_t)bc * HP * HP;
    int chunk = tid >> 7, xcol = tid & 127;

    if (xcol < HP) {
        int y0 = chunk * 28, y1 = min(y0 + 28, HP);
        double s = 0.0;
        for (int y = y0; y < y1; y++) s += (double)h[y * HP + xcol];
        sP[chunk][xcol] = s;
    }
    __syncthreads();

    if (tid < HP) {
        double F = (sP[0][tid] + sP[1][tid]) + (sP[2][tid] + sP[3][tid]);
        double b0 = (double)h[0 * HP + tid], b1 = (double)h[1 * HP + tid];
        double b2 = (double)h[2 * HP + tid], b3 = (double)h[3 * HP + tid];
        double e0 = (double)h[106 * HP + tid], e1 = (double)h[107 * HP + tid];
        double e2 = (double)h[108 * HP + tid], e3 = (double)h[109 * HP + tid];
        sC[0][tid] = F - e0 - e1 - e2 - e3;
        sC[1][tid] = F - b0 - e1 - e2 - e3;
        sC[2][tid] = F - b0 - b1 - e2 - e3;
        sC[3][tid] = F - b0 - b1 - b2 - e3;
        sC[4][tid] = F - b0 - b1 - b2 - b3;
    }
    __syncthreads();

    if (tid < 100) {
        int r = tid >> 2, ch = tid & 3;
        int ky = r / 5, kx = r % 5;
        int x0 = kx + ch * 27, x1 = kx + min(ch * 27 + 27, 106);
        double s = 0.0;
        for (int xx = x0; xx < x1; xx++) s += sC[ky][xx];
        sW[r][ch] = s;
    }
    __syncthreads();

    if (tid < 25)
        g_S[bc * 25 + tid] = (sW[tid][0] + sW[tid][1]) + (sW[tid][2] + sW[tid][3]);
}

// ---------------- K4: head, contiguous slices + fp32 transcendentals ---------
__global__ void __launch_bounds__(256) k_head3(const float* __restrict__ w2,
                                               const float* __restrict__ b2,
                                               const float* __restrict__ f1w,
                                               const float* __restrict__ f1b,
                                               const float* __restrict__ f2w,
                                               const float* __restrict__ f2b,
                                               float* __restrict__ outw) {
    int b = blockIdx.x, tid = threadIdx.x;
    __shared__ double sred[16][15];
    __shared__ double sfeat[16];
    __shared__ double sprod[8][16];
    __shared__ double sh8[8];
    __shared__ float  slog[2];

    if (tid < 240) {
        int o = tid / 15, sl = tid % 15;
        const double* Sp = g_S + b * 150 + sl * 10;
        const float*  Wp = w2 + o * 150 + sl * 10;
        double v[10];
        #pragma unroll
        for (int k = 0; k < 10; k++) v[k] = (double)Wp[k] * Sp[k];
        double s01 = (v[0] + v[1]) + (v[2] + v[3]);
        double s23 = (v[4] + v[5]) + (v[6] + v[7]);
        sred[o][sl] = (s01 + s23) + (v[8] + v[9]);
    }
    __syncthreads();
    if (tid < 16) {
        double s = 0.0;
        #pragma unroll
        for (int k = 0; k < 15; k++) s += sred[tid][k];
        sfeat[tid] = s / 11236.0 + (double)b2[tid];
    }
    __syncthreads();

    if (tid < 128) {
        int j = tid >> 4, q = tid & 15;
        sprod[j][q] = sfeat[q] * (double)f1w[j * 16 + q];
    }
    __syncthreads();
    if (tid < 8) {
        double acc = (double)f1b[tid];
        #pragma unroll
        for (int q = 0; q < 16; q++) acc += sprod[tid][q];
        sh8[tid] = acc > 0.0 ? acc : 0.0;
    }
    __syncthreads();

    if (tid < 2) {
        double acc = (double)f2b[tid];
        #pragma unroll
        for (int j = 0; j < 8; j++) acc += sh8[j] * (double)f2w[tid * 8 + j];
        float wf = 5.0f / (1.0f + expf(-(float)acc));
        outw[b * 2 + tid] = wf;
        float scaled = (tid == 0 ? 0.01f : 0.6f) * wf;
        slog[tid] = logf(scaled);
    }
    __syncthreads();

    float stf = slog[0];
    float dl  = slog[1] - slog[0];
    for (int gy = tid; gy < HG; gy += 256) {
        float t = (float)gy / 319.0f;
        g_radii[b * HG + gy] = expf(stf + dl * t);
    }
}

// ---------------- K5: grid sample, lane=angle, fp16 pair gathers -------------
__global__ void __launch_bounds__(640) k_sample5(const float* __restrict__ lt,
                                                 float* __restrict__ out) {
    __shared__ float s_rad[10];
    __shared__ float s_acc[3][640];
    int b  = blockIdx.y;
    int py = blockIdx.x;
    int t  = threadIdx.x;

    if (t < 10) s_rad[t] = g_radii[b * HG + py * 10 + t];
    __syncthreads();

    float us = g_unit[t * 2 + 0];
    float uc = g_unit[t * 2 + 1];
    float l0 = lt[b * 2 + 0];
    float l1 = lt[b * 2 + 1];
    const __half2* hp  = reinterpret_cast<const __half2*>(g_xh)  + (size_t)b * 3 * (NPIX / 2);
    const __half2* hps = reinterpret_cast<const __half2*>(g_xhs) + (size_t)b * 3 * (NPIX / 2);
    const int RP = NPIX / 2;      // pairs per channel
    const int WP = IMG / 2;       // pairs per row

    float a0 = 0.f, a1 = 0.f, a2 = 0.f;
    #pragma unroll 1
    for (int i = 0; i < 10; i++) {
        float r = s_rad[i];
        float gxx = r * us + l0;
        float gyy = r * uc + l1;
        float ix = ((gxx + 1.0f) * 224.0f - 1.0f) * 0.5f;
        float iy = ((gyy + 1.0f) * 224.0f - 1.0f) * 0.5f;
        float fx = floorf(ix), fy = floorf(iy);
        float wx = ix - fx,   wy = iy - fy;
        int x0 = min(max((int)fx, 0), 223);
        int x1 = min(max((int)fx + 1, 0), 223);
        int y0 = min(max((int)fy, 0), 223);
        int y1 = min(max((int)fy + 1, 0), 223);
        float w00 = (1.f - wx) * (1.f - wy);
        float w01 = wx * (1.f - wy);
        float w10 = (1.f - wx) * wy;
        float w11 = wx * wy;

        int xl = min(x0, 222);
        const __half2* bp = (xl & 1) ? hps : hp;
        int p0 = y0 * WP + (xl >> 1);
        int p1 = y1 * WP + (xl >> 1);
        bool hi0 = (x0 == 223);
        bool dup = (x1 == x0);

        #pragma unroll
        for (int c = 0; c < 3; c++) {
            float2 A  = __half22float2(__ldg(bp + c * RP + p0));
            float2 Bv = __half22float2(__ldg(bp + c * RP + p1));
            float v00 = hi0 ? A.y : A.x;
            float v01 = dup ? v00 : A.y;
            float v10 = hi0 ? Bv.y : Bv.x;
            float v11 = dup ? v10 : Bv.y;
            float sv = w00 * v00 + w01 * v01 + w10 * v10 + w11 * v11;
            if (c == 0) a0 += sv;
            else if (c == 1) a1 += sv;
            else a2 += sv;
        }
    }
    s_acc[0][t] = a0;
    s_acc[1][t] = a1;
    s_acc[2][t] = a2;
    __syncthreads();

    if (t < 192) {
        int c = t / 64, pw = t % 64;
        const float* sp = &s_acc[c][pw * 10];
        float s = 0.f;
        #pragma unroll
        for (int j = 0; j < 10; j++) s += sp[j];
        out[(((size_t)b * 3 + c) * 32 + py) * 64 + pw] = s * 0.01f;
    }
}

// ---------------- launch ------------------------------------------------------
extern "C" void kernel_launch(void* const* d_in, const int* in_sizes, int n_in,
                              void* d_out, int out_size) {
    const float* x   = (const float*)d_in[0];
    const float* lt  = (const float*)d_in[1];
    const float* c1w = (const float*)d_in[2];
    const float* c1b = (const float*)d_in[3];
    const float* c2w = (const float*)d_in[4];
    const float* c2b = (const float*)d_in[5];
    const float* f1w = (const float*)d_in[6];
    const float* f1b = (const float*)d_in[7];
    const float* f2w = (const float*)d_in[8];
    const float* f2b = (const float*)d_in[9];
    float* out = (float*)d_out;

    k_shift_unit<<<9411, 256>>>(x);                                        // #1
    k_nop1<<<1, 32>>>();                                                   // #2
    k_nop2<<<1, 32>>>();                                                   // #3
    k_conv1_v6<<<dim3(48, 2, NB), 128>>>(x, c1w, c1b);                     // #4 -> profiled
    k_winsum3<<<NB * 6, 512>>>();                                          // #5
    k_head3<<<NB, 256>>>(c2w, c2b, f1w, f1b, f2w, f2b,
                         out + 64 * 3 * 32 * 64);                          // #6
    k_sample5<<<dim3(32, NB), 640>>>(lt, out);                             // #7
}

// round 17
// speedup vs baseline: 1.2995x; 1.0660x over previous
#include <cuda_runtime.h>
#include <cuda_fp16.h>
#include <math.h>

#define NB 64
#define IMG 224
#define HP 110
#define NPIX (IMG*IMG)
#define HG 320
#define WG 640

typedef unsigned long long ull;

// ---------------- scratch ----------------------------------------------------
__device__ float  g_xs[(size_t)NB * 3 * NPIX];      // x shifted by one (fp32, conv)
__device__ ull    g_xn [(size_t)NB * NPIX];         // NHWC4 fp16 pixels (c0,c1,c2,0)
__device__ ull    g_xns[(size_t)NB * NPIX];         // NHWC4 fp16, shifted 1 pixel
__device__ float  g_h1[(size_t)NB * 6 * HP * HP];
__device__ double g_S[NB * 6 * 25];
__device__ float  g_radii[NB * HG];
__device__ float  g_unit[WG * 2];

// ---------------- f32x2 helpers ----------------------------------------------
__device__ __forceinline__ ull pk(float lo, float hi) {
    ull r; asm("mov.b64 %0,{%1,%2};" : "=l"(r) : "f"(lo), "f"(hi)); return r;
}
__device__ __forceinline__ float2 unpk(ull v) {
    float2 r; asm("mov.b64 {%0,%1},%2;" : "=f"(r.x), "=f"(r.y) : "l"(v)); return r;
}
__device__ __forceinline__ void fma2(ull& d, ull a, ull b) {
    asm("fma.rn.f32x2 %0,%1,%2,%0;" : "+l"(d) : "l"(a), "l"(b));
}
__device__ __forceinline__ float2 h22f2(unsigned u) {
    __half2 h = *reinterpret_cast<__half2*>(&u);
    return __half22float2(h);
}

// ---------------- K1: xs + NHWC fp16 + unit table ----------------------------
__global__ void k_prep(const float* __restrict__ x) {
    int blk = blockIdx.x;
    if (blk < 9408) {                      // role A: fp32 shifted pairs for conv
        int gid = blk * 256 + threadIdx.x;
        const int total = NB * 3 * NPIX / 4;
        float4 q0 = __ldg(reinterpret_cast<const float4*>(x) + gid);
        float4 q1 = make_float4(0.f, 0.f, 0.f, 0.f);
        if (gid + 1 < total) q1 = __ldg(reinterpret_cast<const float4*>(x) + gid + 1);
        float4 o; o.x = q0.y; o.y = q0.z; o.z = q0.w; o.w = q1.x;
        reinterpret_cast<float4*>(g_xs)[gid] = o;
        return;
    }
    if (blk < 9408 + 12544) {              // role B: NHWC4 fp16 (+shifted)
        int idx = blk - 9408;
        int b = idx / 196;
        int pos = (idx % 196) * 256 + threadIdx.x;   // 0..50175
        const float* xb = x + (size_t)b * 3 * NPIX;
        float c0 = __ldg(xb + pos);
        float c1 = __ldg(xb + NPIX + pos);
        float c2 = __ldg(xb + 2 * NPIX + pos);
        __half2 h01 = __floats2half2_rn(c0, c1);
        __half2 h2  = __floats2half2_rn(c2, 0.f);
        uint2 pix;
        pix.x = *reinterpret_cast<unsigned*>(&h01);
        pix.y = *reinterpret_cast<unsigned*>(&h2);
        size_t base = (size_t)b * NPIX;
        reinterpret_cast<uint2*>(g_xn)[base + pos] = pix;
        if (pos > 0)
            reinterpret_cast<uint2*>(g_xns)[base + pos - 1] = pix;
        return;
    }
    {                                       // role C: unit table
        int gx = (blk - 9408 - 12544) * 256 + threadIdx.x;
        if (gx < WG) {
            float af = (float)(2.0 * M_PI) * (float)gx / 640.0f;
            g_unit[gx * 2 + 0] = sinf(af);
            g_unit[gx * 2 + 1] = cosf(af);
        }
    }
}

// ---------------- K2: conv1 + maxpool, co-split for occupancy ----------------
__device__ __forceinline__ void loadrow(ull* P, const float* xrow, const float* xsrow) {
    longlong2 e01 = __ldg(reinterpret_cast<const longlong2*>(xrow));
    longlong2 e23 = __ldg(reinterpret_cast<const longlong2*>(xrow) + 1);
    longlong2 o01 = __ldg(reinterpret_cast<const longlong2*>(xsrow));
    ull       o2  = __ldg(reinterpret_cast<const ull*>(xsrow) + 2);
    P[0] = (ull)e01.x; P[1] = (ull)o01.x; P[2] = (ull)e01.y; P[3] = (ull)o01.y;
    P[4] = (ull)e23.x; P[5] = o2;         P[6] = (ull)e23.y;
}

__global__ void __launch_bounds__(128) k_conv1_v6(const float* __restrict__ x,
                                                  const float* __restrict__ w,
                                                  const float* __restrict__ bia) {
    __shared__ __align__(16) ull swd[300];
    __shared__ float sb[3];
    int tid = threadIdx.x;
    int cog = blockIdx.y;
    for (int i = tid; i < 225; i += 128) {
        int co = i / 75, r = i % 75;
        float ww = w[(cog * 3 + co) * 75 + r];
        swd[r * 4 + co] = pk(ww, ww);
    }
    if (tid < 3) sb[tid] = bia[cog * 3 + tid];
    __syncthreads();

    int b = blockIdx.z;
    int pos2 = blockIdx.x * 128 + tid;
    if (pos2 >= 55 * HP) return;
    int py = pos2 / 55, pxp = pos2 % 55;
    int px0 = 2 * pxp;
    size_t rowoff = (size_t)(2 * py) * IMG + 4 * pxp;
    const float* xb  = x    + (size_t)b * 3 * NPIX + rowoff;
    const float* xsb = g_xs + (size_t)b * 3 * NPIX + rowoff;

    ull acc[3][4];
    #pragma unroll
    for (int co = 0; co < 3; co++)
        #pragma unroll
        for (int q = 0; q < 4; q++) acc[co][q] = 0ull;

    #pragma unroll 1
    for (int ci = 0; ci < 3; ci++) {
        const float* xc  = xb  + (size_t)ci * NPIX;
        const float* xsc = xsb + (size_t)ci * NPIX;
        ull P[2][7];
        loadrow(P[0], xc, xsc);
        #pragma unroll
        for (int ky = 0; ky < 5; ky++) {
            loadrow(P[(ky + 1) & 1], xc + (ky + 1) * IMG, xsc + (ky + 1) * IMG);
            const ull* PA = P[ky & 1];
            const ull* PB = P[(ky + 1) & 1];
            #pragma unroll
            for (int kx = 0; kx < 5; kx++) {
                const ull* wr = swd + (ci * 25 + ky * 5 + kx) * 4;
                ulonglong2 w01 = *reinterpret_cast<const ulonglong2*>(wr);
                ull        w2v = wr[2];
                ull pa = PA[kx], pb = PB[kx], pa2 = PA[kx + 2], pb2 = PB[kx + 2];
                fma2(acc[0][0], pa, w01.x); fma2(acc[0][1], pb, w01.x);
                fma2(acc[0][2], pa2, w01.x); fma2(acc[0][3], pb2, w01.x);
                fma2(acc[1][0], pa, w01.y); fma2(acc[1][1], pb, w01.y);
                fma2(acc[1][2], pa2, w01.y); fma2(acc[1][3], pb2, w01.y);
                fma2(acc[2][0], pa, w2v);   fma2(acc[2][1], pb, w2v);
                fma2(acc[2][2], pa2, w2v);  fma2(acc[2][3], pb2, w2v);
            }
        }
    }
    #pragma unroll
    for (int co = 0; co < 3; co++) {
        float2 u0 = unpk(acc[co][0]);
        float2 u1 = unpk(acc[co][1]);
        float2 u2 = unpk(acc[co][2]);
        float2 u3 = unpk(acc[co][3]);
        float2 m;
        m.x = fmaxf(fmaxf(u0.x, u0.y), fmaxf(u1.x, u1.y)) + sb[co];
        m.y = fmaxf(fmaxf(u2.x, u2.y), fmaxf(u3.x, u3.y)) + sb[co];
        *reinterpret_cast<float2*>(
            g_h1 + ((size_t)b * 6 + cog * 3 + co) * (HP * HP) + (size_t)py * HP + px0) = m;
    }
}

// ---------------- K3: winsum, chunk-parallel (double), 384 blocks ------------
__global__ void __launch_bounds__(512) k_winsum3() {
    int bc = blockIdx.x;
    int tid = threadIdx.x;
    __shared__ double sP[4][112];
    __shared__ double sC[5][112];
    __shared__ double sW[25][4];

    const float* h = g_h1 + (size_t)bc * HP * HP;
    int chunk = tid >> 7, xcol = tid & 127;

    if (xcol < HP) {
        int y0 = chunk * 28, y1 = min(y0 + 28, HP);
        double s = 0.0;
        for (int y = y0; y < y1; y++) s += (double)h[y * HP + xcol];
        sP[chunk][xcol] = s;
    }
    __syncthreads();

    if (tid < HP) {
        double F = (sP[0][tid] + sP[1][tid]) + (sP[2][tid] + sP[3][tid]);
        double b0 = (double)h[0 * HP + tid], b1 = (double)h[1 * HP + tid];
        double b2 = (double)h[2 * HP + tid], b3 = (double)h[3 * HP + tid];
        double e0 = (double)h[106 * HP + tid], e1 = (double)h[107 * HP + tid];
        double e2 = (double)h[108 * HP + tid], e3 = (double)h[109 * HP + tid];
        sC[0][tid] = F - e0 - e1 - e2 - e3;
        sC[1][tid] = F - b0 - e1 - e2 - e3;
        sC[2][tid] = F - b0 - b1 - e2 - e3;
        sC[3][tid] = F - b0 - b1 - b2 - e3;
        sC[4][tid] = F - b0 - b1 - b2 - b3;
    }
    __syncthreads();

    if (tid < 100) {
        int r = tid >> 2, ch = tid & 3;
        int ky = r / 5, kx = r % 5;
        int x0 = kx + ch * 27, x1 = kx + min(ch * 27 + 27, 106);
        double s = 0.0;
        for (int xx = x0; xx < x1; xx++) s += sC[ky][xx];
        sW[r][ch] = s;
    }
    __syncthreads();

    if (tid < 25)
        g_S[bc * 25 + tid] = (sW[tid][0] + sW[tid][1]) + (sW[tid][2] + sW[tid][3]);
}

// ---------------- K4: head, contiguous slices + fp32 transcendentals ---------
__global__ void __launch_bounds__(256) k_head3(const float* __restrict__ w2,
                                               const float* __restrict__ b2,
                                               const float* __restrict__ f1w,
                                               const float* __restrict__ f1b,
                                               const float* __restrict__ f2w,
                                               const float* __restrict__ f2b,
                                               float* __restrict__ outw) {
    int b = blockIdx.x, tid = threadIdx.x;
    __shared__ double sred[16][15];
    __shared__ double sfeat[16];
    __shared__ double sprod[8][16];
    __shared__ double sh8[8];
    __shared__ float  slog[2];

    if (tid < 240) {
        int o = tid / 15, sl = tid % 15;
        const double* Sp = g_S + b * 150 + sl * 10;
        const float*  Wp = w2 + o * 150 + sl * 10;
        double v[10];
        #pragma unroll
        for (int k = 0; k < 10; k++) v[k] = (double)Wp[k] * Sp[k];
        double s01 = (v[0] + v[1]) + (v[2] + v[3]);
        double s23 = (v[4] + v[5]) + (v[6] + v[7]);
        sred[o][sl] = (s01 + s23) + (v[8] + v[9]);
    }
    __syncthreads();
    if (tid < 16) {
        double s = 0.0;
        #pragma unroll
        for (int k = 0; k < 15; k++) s += sred[tid][k];
        sfeat[tid] = s / 11236.0 + (double)b2[tid];
    }
    __syncthreads();

    if (tid < 128) {
        int j = tid >> 4, q = tid & 15;
        sprod[j][q] = sfeat[q] * (double)f1w[j * 16 + q];
    }
    __syncthreads();
    if (tid < 8) {
        double acc = (double)f1b[tid];
        #pragma unroll
        for (int q = 0; q < 16; q++) acc += sprod[tid][q];
        sh8[tid] = acc > 0.0 ? acc : 0.0;
    }
    __syncthreads();

    if (tid < 2) {
        double acc = (double)f2b[tid];
        #pragma unroll
        for (int j = 0; j < 8; j++) acc += sh8[j] * (double)f2w[tid * 8 + j];
        float wf = 5.0f / (1.0f + expf(-(float)acc));
        outw[b * 2 + tid] = wf;
        float scaled = (tid == 0 ? 0.01f : 0.6f) * wf;
        slog[tid] = logf(scaled);
    }
    __syncthreads();

    float stf = slog[0];
    float dl  = slog[1] - slog[0];
    for (int gy = tid; gy < HG; gy += 256) {
        float t = (float)gy / 319.0f;
        g_radii[b * HG + gy] = expf(stf + dl * t);
    }
}

// ---------------- K5: grid sample, NHWC4 fp16, 2 LDG.128 per tap -------------
__global__ void __launch_bounds__(640) k_sample6(const float* __restrict__ lt,
                                                 float* __restrict__ out) {
    __shared__ float s_rad[10];
    __shared__ float s_acc[3][640];
    int b  = blockIdx.y;
    int py = blockIdx.x;
    int t  = threadIdx.x;

    if (t < 10) s_rad[t] = g_radii[b * HG + py * 10 + t];
    __syncthreads();

    float us = g_unit[t * 2 + 0];
    float uc = g_unit[t * 2 + 1];
    float l0 = lt[b * 2 + 0];
    float l1 = lt[b * 2 + 1];
    const uint4* pn  = reinterpret_cast<const uint4*>(g_xn)  + (size_t)b * (NPIX / 2);
    const uint4* pns = reinterpret_cast<const uint4*>(g_xns) + (size_t)b * (NPIX / 2);
    const int WPQ = IMG / 2;   // uint4 (=2 pixels) per row

    float a0 = 0.f, a1 = 0.f, a2 = 0.f;
    #pragma unroll 1
    for (int i = 0; i < 10; i++) {
        float r = s_rad[i];
        float gxx = r * us + l0;
        float gyy = r * uc + l1;
        float ix = ((gxx + 1.0f) * 224.0f - 1.0f) * 0.5f;
        float iy = ((gyy + 1.0f) * 224.0f - 1.0f) * 0.5f;
        float fx = floorf(ix), fy = floorf(iy);
        float wx = ix - fx,   wy = iy - fy;
        int x0 = min(max((int)fx, 0), 223);
        int x1 = min(max((int)fx + 1, 0), 223);
        int y0 = min(max((int)fy, 0), 223);
        int y1 = min(max((int)fy + 1, 0), 223);
        float w00 = (1.f - wx) * (1.f - wy);
        float w01 = wx * (1.f - wy);
        float w10 = (1.f - wx) * wy;
        float w11 = wx * wy;

        int xl = min(x0, 222);
        const uint4* bp = (xl & 1) ? pns : pn;
        bool hi0 = (x0 == 223);
        bool dup = (x1 == x0);

        uint4 A = __ldg(bp + y0 * WPQ + (xl >> 1));
        uint4 B = __ldg(bp + y1 * WPQ + (xl >> 1));

        unsigned P0a = hi0 ? A.z : A.x,  P0b = hi0 ? A.w : A.y;   // top pixel x0
        unsigned P1a = dup ? P0a : A.z,  P1b = dup ? P0b : A.w;   // top pixel x1
        unsigned Q0a = hi0 ? B.z : B.x,  Q0b = hi0 ? B.w : B.y;   // bot pixel x0
        unsigned Q1a = dup ? Q0a : B.z,  Q1b = dup ? Q0b : B.w;   // bot pixel x1

        float2 p0c = h22f2(P0a); float2 p0e = h22f2(P0b);
        float2 p1c = h22f2(P1a); float2 p1e = h22f2(P1b);
        float2 q0c = h22f2(Q0a); float2 q0e = h22f2(Q0b);
        float2 q1c = h22f2(Q1a); float2 q1e = h22f2(Q1b);

        a0 += w00 * p0c.x + w01 * p1c.x + w10 * q0c.x + w11 * q1c.x;
        a1 += w00 * p0c.y + w01 * p1c.y + w10 * q0c.y + w11 * q1c.y;
        a2 += w00 * p0e.x + w01 * p1e.x + w10 * q0e.x + w11 * q1e.x;
    }
    s_acc[0][t] = a0;
    s_acc[1][t] = a1;
    s_acc[2][t] = a2;
    __syncthreads();

    if (t < 192) {
        int c = t / 64, pw = t % 64;
        const float* sp = &s_acc[c][pw * 10];
        float s = 0.f;
        #pragma unroll
        for (int j = 0; j < 10; j++) s += sp[j];
        out[(((size_t)b * 3 + c) * 32 + py) * 64 + pw] = s * 0.01f;
    }
}

// ---------------- launch ------------------------------------------------------
extern "C" void kernel_launch(void* const* d_in, const int* in_sizes, int n_in,
                              void* d_out, int out_size) {
    const float* x   = (const float*)d_in[0];
    const float* lt  = (const float*)d_in[1];
    const float* c1w = (const float*)d_in[2];
    const float* c1b = (const float*)d_in[3];
    const float* c2w = (const float*)d_in[4];
    const float* c2b = (const float*)d_in[5];
    const float* f1w = (const float*)d_in[6];
    const float* f1b = (const float*)d_in[7];
    const float* f2w = (const float*)d_in[8];
    const float* f2b = (const float*)d_in[9];
    float* out = (float*)d_out;

    k_prep<<<9408 + 12544 + 3, 256>>>(x);                                  // #1
    k_conv1_v6<<<dim3(48, 2, NB), 128>>>(x, c1w, c1b);                     // #2
    k_winsum3<<<NB * 6, 512>>>();                                          // #3
    k_head3<<<NB, 256>>>(c2w, c2b, f1w, f1b, f2w, f2b,
                         out + 64 * 3 * 32 * 64);                          // #4 -> profiled
    k_sample6<<<dim3(32, NB), 640>>>(lt, out);                             // #5
}